// round 3
// baseline (speedup 1.0000x reference)
#include <cuda_runtime.h>
#include <math.h>

// Problem constants
#define NROWS   65536      // 64*1024 vectors
#define DIM     64
#define KC      512
#define NQ      (NROWS*DIM)
#define THREADS 256
#define STRIDE4 17                     // float4 stride per code row (68 floats, pad 4)
#define STRIDEF (STRIDE4*4)            // 68 floats
#define SMEM_FLOATS (KC*STRIDEF + KC)  // padded embedding + norms

// Output layout (flattened tuple, f32):
//   [0] loss | [1..NQ] quantized_st (UNALIGNED base) | [1+NQ] perplexity
//   [2+NQ ..] indices (as float)

__device__ double       g_sse;
__device__ int          g_hist[KC];
__device__ unsigned int g_done;

// ---- packed f32x2 helpers (PTX-only; ptxas never auto-fuses) ----------------
__device__ __forceinline__ unsigned long long pk2(float lo, float hi) {
    unsigned long long r;
    asm("mov.b64 %0, {%1, %2};" : "=l"(r) : "f"(lo), "f"(hi));
    return r;
}
__device__ __forceinline__ void upk2(unsigned long long v, float& lo, float& hi) {
    asm("mov.b64 {%0, %1}, %2;" : "=f"(lo), "=f"(hi) : "l"(v));
}
__device__ __forceinline__ unsigned long long fma2(unsigned long long a,
                                                   unsigned long long b,
                                                   unsigned long long c) {
    unsigned long long d;
    asm("fma.rn.f32x2 %0, %1, %2, %3;" : "=l"(d) : "l"(a), "l"(b), "l"(c));
    return d;
}
__device__ __forceinline__ unsigned long long add2(unsigned long long a,
                                                   unsigned long long b) {
    unsigned long long d;
    asm("add.rn.f32x2 %0, %1, %2;" : "=l"(d) : "l"(a), "l"(b));
    return d;
}

__global__ void init_kernel() {
    int t = blockIdx.x * blockDim.x + threadIdx.x;
    if (t < KC) g_hist[t] = 0;
    if (t == 0) { g_sse = 0.0; g_done = 0u; }
}

// -----------------------------------------------------------------------------
// Fused kernel: argmin (packed-f32x2 FMA) + gather/ST output + SSE + hist,
// with finalize (loss/perplexity) executed by the last block to finish.
//
// Numerics replicate JAX where it decides the result:
//   d_k = fl( fl(A + b_k) - 2*c_k ),  first-index tie-break (strict <, k asc).
// Reduction-order noise (~1e-9) is far below the ULP(64)=7.6e-6 grid that the
// distances are rounded onto (validated R2: zero index mismatches).
// -----------------------------------------------------------------------------
__global__ void __launch_bounds__(THREADS)
vq_fused_kernel(const float* __restrict__ inp,
                const float* __restrict__ emb,
                float* __restrict__ out)
{
    extern __shared__ float smem[];
    float* sE = smem;                 // KC rows, padded stride 68 floats
    float* sB = smem + KC * STRIDEF;  // KC squared norms

    // Load embedding into padded smem (float4, conflict-spreading stride)
    for (int i = threadIdx.x; i < KC * DIM / 4; i += THREADS) {
        int k = i >> 4, j = i & 15;
        reinterpret_cast<float4*>(sE)[k * STRIDE4 + j] =
            reinterpret_cast<const float4*>(emb)[i];
    }
    __syncthreads();

    // Per-code squared norms
    for (int k = threadIdx.x; k < KC; k += THREADS) {
        const float* e = sE + k * STRIDEF;
        float b0 = 0.f, b1 = 0.f;
        #pragma unroll
        for (int i = 0; i < DIM; i += 2) {
            b0 = fmaf(e[i],     e[i],     b0);
            b1 = fmaf(e[i + 1], e[i + 1], b1);
        }
        sB[k] = b0 + b1;
    }
    __syncthreads();

    const int row = blockIdx.x * THREADS + threadIdx.x;

    // Load + pack the row: 64 floats -> 32 packed f32x2 regs; packed A accum
    unsigned long long x2[32];
    float A;
    {
        const float4* xin = reinterpret_cast<const float4*>(inp + (size_t)row * DIM);
        unsigned long long a0 = 0ull, a1 = 0ull, a2 = 0ull, a3 = 0ull;
        #pragma unroll
        for (int i = 0; i < 16; i++) {
            float4 v = xin[i];
            unsigned long long p0 = pk2(v.x, v.y);
            unsigned long long p1 = pk2(v.z, v.w);
            x2[2 * i]     = p0;
            x2[2 * i + 1] = p1;
            if (i & 1) { a2 = fma2(p0, p0, a2); a3 = fma2(p1, p1, a3); }
            else       { a0 = fma2(p0, p0, a0); a1 = fma2(p1, p1, a1); }
        }
        unsigned long long s0 = add2(a0, a2), s1 = add2(a1, a3);
        float p, q, r, s;
        upk2(s0, p, q); upk2(s1, r, s);
        A = (p + r) + (q + s);
    }

    float best = 3.402823466e+38f;
    int   bi   = 0;

    #pragma unroll 2
    for (int k = 0; k < KC; k++) {
        const ulonglong2* e2 =
            reinterpret_cast<const ulonglong2*>(sE + k * STRIDEF);
        unsigned long long a0 = 0ull, a1 = 0ull, a2 = 0ull, a3 = 0ull;
        #pragma unroll
        for (int j = 0; j < 16; j++) {
            ulonglong2 ev = e2[j];        // LDS.128, broadcast across lanes
            if (j & 1) {
                a2 = fma2(x2[2 * j],     ev.x, a2);
                a3 = fma2(x2[2 * j + 1], ev.y, a3);
            } else {
                a0 = fma2(x2[2 * j],     ev.x, a0);
                a1 = fma2(x2[2 * j + 1], ev.y, a1);
            }
        }
        unsigned long long s0 = add2(a0, a2), s1 = add2(a1, a3);
        float p, q, r, s;
        upk2(s0, p, q); upk2(s1, r, s);
        float c  = (p + r) + (q + s);
        float t  = A + sB[k];            // fl(A + b_k)
        float dd = t - 2.0f * c;         // fl(t - 2c); contraction exact-equal
        if (dd < best) { best = dd; bi = k; }
    }

    // ---- fused epilogue: indices, hist, quantized_st, SSE -------------------
    out[2 + NQ + row] = (float)bi;
    atomicAdd(&g_hist[bi], 1);

    float* q = out + 1 + (size_t)row * DIM;   // 4B-aligned only -> scalar stores
    const float4* eb = reinterpret_cast<const float4*>(sE + bi * STRIDEF);
    float sse = 0.f;
    #pragma unroll
    for (int j = 0; j < 16; j++) {
        float4 ev = eb[j];                    // padded stride -> ~4-way conflicts
        float xl0, xh0, xl1, xh1;
        upk2(x2[2 * j], xl0, xh0);
        upk2(x2[2 * j + 1], xl1, xh1);
        float d0 = ev.x - xl0, d1 = ev.y - xh0;
        float d2 = ev.z - xl1, d3 = ev.w - xh1;
        q[4 * j + 0] = xl0 + d0;              // fl(x + fl(q-x)) exactly
        q[4 * j + 1] = xh0 + d1;
        q[4 * j + 2] = xl1 + d2;
        q[4 * j + 3] = xh1 + d3;
        sse += d0 * d0 + d1 * d1 + d2 * d2 + d3 * d3;
    }
    #pragma unroll
    for (int off = 16; off > 0; off >>= 1)
        sse += __shfl_xor_sync(0xFFFFFFFFu, sse, off);
    if ((threadIdx.x & 31) == 0)
        atomicAdd(&g_sse, (double)sse);

    // ---- last block finalizes loss & perplexity ----------------------------
    __threadfence();     // publish this thread's atomics at gpu scope
    __syncthreads();
    __shared__ unsigned int s_last;
    if (threadIdx.x == 0)
        s_last = (atomicAdd(&g_done, 1u) == gridDim.x - 1u) ? 1u : 0u;
    __syncthreads();
    if (s_last) {
        __threadfence();  // acquire side
        __shared__ float red[THREADS];
        float acc = 0.f;
        for (int b = threadIdx.x; b < KC; b += THREADS) {
            float pb = (float)g_hist[b] * (1.0f / (float)NROWS);
            acc += pb * logf(pb + 1e-10f);
        }
        red[threadIdx.x] = acc;
        __syncthreads();
        for (int off = THREADS / 2; off > 0; off >>= 1) {
            if (threadIdx.x < off) red[threadIdx.x] += red[threadIdx.x + off];
            __syncthreads();
        }
        if (threadIdx.x == 0) {
            out[0]      = (float)(1.25 * (g_sse * (1.0 / (double)NQ)));
            out[1 + NQ] = expf(-red[0]);
        }
    }
}

extern "C" void kernel_launch(void* const* d_in, const int* in_sizes, int n_in,
                              void* d_out, int out_size)
{
    const float* inp = (const float*)d_in[0];
    const float* emb = (const float*)d_in[1];
    if (n_in >= 2 && in_sizes[0] == KC * DIM) {  // defensive: order swapped
        const float* t = inp; inp = emb; emb = t;
    }
    float* out = (float*)d_out;

    const int smem_bytes = SMEM_FLOATS * sizeof(float);  // 141,312 B
    cudaFuncSetAttribute(vq_fused_kernel,
                         cudaFuncAttributeMaxDynamicSharedMemorySize,
                         smem_bytes);

    init_kernel<<<1, 512>>>();
    vq_fused_kernel<<<NROWS / THREADS, THREADS, smem_bytes>>>(inp, emb, out);
}

// round 4
// speedup vs baseline: 1.4012x; 1.4012x over previous
#include <cuda_runtime.h>
#include <math.h>

// Problem constants
#define NROWS   65536
#define DIM     64
#define KC      512
#define NQ      (NROWS*DIM)
#define THREADS 256
#define RPT     2                       // rows per thread
#define ROWS_PER_BLOCK (THREADS*RPT)    // 512
#define GRID    (NROWS/ROWS_PER_BLOCK)  // 128
#define STRIDE4 17                      // float4 stride per code row (68 floats)
#define STRIDEF (STRIDE4*4)
#define SMEM_FLOATS (KC*STRIDEF + KC)

// Output layout (flattened tuple, f32):
//   [0] loss | [1..NQ] quantized_st (base out+1, 4B-aligned only)
//   [1+NQ] perplexity | [2+NQ..] indices (as float)

__device__ double       g_sse;
__device__ int          g_hist[KC];
__device__ unsigned int g_done;

// ---- packed f32x2 helpers ---------------------------------------------------
__device__ __forceinline__ unsigned long long pk2(float lo, float hi) {
    unsigned long long r;
    asm("mov.b64 %0, {%1, %2};" : "=l"(r) : "f"(lo), "f"(hi));
    return r;
}
__device__ __forceinline__ void upk2(unsigned long long v, float& lo, float& hi) {
    asm("mov.b64 {%0, %1}, %2;" : "=f"(lo), "=f"(hi) : "l"(v));
}
__device__ __forceinline__ unsigned long long fma2(unsigned long long a,
                                                   unsigned long long b,
                                                   unsigned long long c) {
    unsigned long long d;
    asm("fma.rn.f32x2 %0, %1, %2, %3;" : "=l"(d) : "l"(a), "l"(b), "l"(c));
    return d;
}
__device__ __forceinline__ unsigned long long add2(unsigned long long a,
                                                   unsigned long long b) {
    unsigned long long d;
    asm("add.rn.f32x2 %0, %1, %2;" : "=l"(d) : "l"(a), "l"(b));
    return d;
}

__global__ void init_kernel() {
    int t = blockIdx.x * blockDim.x + threadIdx.x;
    if (t < KC) g_hist[t] = 0;
    if (t == 0) { g_sse = 0.0; g_done = 0u; }
}

// ---- per-row helpers --------------------------------------------------------
__device__ __forceinline__ float load_row_packed(const float* __restrict__ inp,
                                                 int row, unsigned long long* x2) {
    const float4* xin = reinterpret_cast<const float4*>(inp + (size_t)row * DIM);
    unsigned long long a0 = 0ull, a1 = 0ull;
    #pragma unroll
    for (int i = 0; i < 16; i++) {
        float4 v = xin[i];
        unsigned long long p0 = pk2(v.x, v.y);
        unsigned long long p1 = pk2(v.z, v.w);
        x2[2 * i]     = p0;
        x2[2 * i + 1] = p1;
        a0 = fma2(p0, p0, a0);
        a1 = fma2(p1, p1, a1);
    }
    float p, q;
    unsigned long long s = add2(a0, a1);
    upk2(s, p, q);
    return p + q;   // A = sum(x*x); order-noise is below the ULP(64) d-grid
}

// Epilogue for one row: quantized_st = fl(x + fl(q-x)), SSE accumulation.
// Destination row base is (out+1)+64*row == 4 (mod 16): cols 3..62 go out as
// 15 aligned float4 stores, cols 0,1,2,63 scalar.
__device__ __forceinline__ float row_epilogue(const float* __restrict__ sE,
                                              const unsigned long long* x2,
                                              int bi, float* __restrict__ q) {
    const float4* eb = reinterpret_cast<const float4*>(sE + bi * STRIDEF);
    float qs[64];
    float sse = 0.f;
    #pragma unroll
    for (int j = 0; j < 16; j++) {
        float4 ev = eb[j];                 // padded stride -> spread conflicts
        float xl0, xh0, xl1, xh1;
        upk2(x2[2 * j],     xl0, xh0);
        upk2(x2[2 * j + 1], xl1, xh1);
        float d0 = ev.x - xl0, d1 = ev.y - xh0;
        float d2 = ev.z - xl1, d3 = ev.w - xh1;
        qs[4 * j + 0] = xl0 + d0;
        qs[4 * j + 1] = xh0 + d1;
        qs[4 * j + 2] = xl1 + d2;
        qs[4 * j + 3] = xh1 + d3;
        sse += d0 * d0 + d1 * d1 + d2 * d2 + d3 * d3;
    }
    q[0] = qs[0]; q[1] = qs[1]; q[2] = qs[2];
    float4* q4 = reinterpret_cast<float4*>(q + 3);   // 16B aligned
    #pragma unroll
    for (int i = 0; i < 15; i++)
        q4[i] = make_float4(qs[3 + 4 * i], qs[4 + 4 * i],
                            qs[5 + 4 * i], qs[6 + 4 * i]);
    q[63] = qs[63];
    return sse;
}

// -----------------------------------------------------------------------------
// Fused kernel: 2-row register-blocked argmin + gather/ST + SSE + hist,
// last block computes loss & perplexity.
// -----------------------------------------------------------------------------
__global__ void __launch_bounds__(THREADS)
vq_fused_kernel(const float* __restrict__ inp,
                const float* __restrict__ emb,
                float* __restrict__ out)
{
    extern __shared__ float smem[];
    float* sE = smem;                 // KC rows, stride 68 floats
    float* sB = smem + KC * STRIDEF;  // KC squared norms

    // Load embedding into padded smem
    for (int i = threadIdx.x; i < KC * DIM / 4; i += THREADS) {
        int k = i >> 4, j = i & 15;
        reinterpret_cast<float4*>(sE)[k * STRIDE4 + j] =
            reinterpret_cast<const float4*>(emb)[i];
    }
    __syncthreads();

    for (int k = threadIdx.x; k < KC; k += THREADS) {
        const float* e = sE + k * STRIDEF;
        float b0 = 0.f, b1 = 0.f;
        #pragma unroll
        for (int i = 0; i < DIM; i += 2) {
            b0 = fmaf(e[i],     e[i],     b0);
            b1 = fmaf(e[i + 1], e[i + 1], b1);
        }
        sB[k] = b0 + b1;
    }
    __syncthreads();

    const int row0 = blockIdx.x * ROWS_PER_BLOCK + threadIdx.x;
    const int row1 = row0 + THREADS;

    unsigned long long x0[32], x1[32];
    const float A0 = load_row_packed(inp, row0, x0);
    const float A1 = load_row_packed(inp, row1, x1);

    float best0 = 3.402823466e+38f, best1 = 3.402823466e+38f;
    int   bi0   = 0,                bi1   = 0;

    #pragma unroll 2
    for (int k = 0; k < KC; k++) {
        const ulonglong2* e2 =
            reinterpret_cast<const ulonglong2*>(sE + k * STRIDEF);
        unsigned long long a0 = 0ull, a1 = 0ull;   // row0 chains
        unsigned long long b0 = 0ull, b1 = 0ull;   // row1 chains
        #pragma unroll
        for (int j = 0; j < 16; j++) {
            ulonglong2 ev = e2[j];       // one LDS.128 feeds BOTH rows
            a0 = fma2(x0[2 * j],     ev.x, a0);
            a1 = fma2(x0[2 * j + 1], ev.y, a1);
            b0 = fma2(x1[2 * j],     ev.x, b0);
            b1 = fma2(x1[2 * j + 1], ev.y, b1);
        }
        float bk = sB[k];
        {
            unsigned long long s = add2(a0, a1);
            float p, q; upk2(s, p, q);
            float c  = p + q;
            float t  = A0 + bk;          // fl(A + b_k)
            float dd = t - 2.0f * c;     // fl(t - 2c)
            if (dd < best0) { best0 = dd; bi0 = k; }
        }
        {
            unsigned long long s = add2(b0, b1);
            float p, q; upk2(s, p, q);
            float c  = p + q;
            float t  = A1 + bk;
            float dd = t - 2.0f * c;
            if (dd < best1) { best1 = dd; bi1 = k; }
        }
    }

    // ---- fused epilogue -----------------------------------------------------
    out[2 + NQ + row0] = (float)bi0;
    out[2 + NQ + row1] = (float)bi1;
    atomicAdd(&g_hist[bi0], 1);
    atomicAdd(&g_hist[bi1], 1);

    float sse = row_epilogue(sE, x0, bi0, out + 1 + (size_t)row0 * DIM)
              + row_epilogue(sE, x1, bi1, out + 1 + (size_t)row1 * DIM);

    #pragma unroll
    for (int off = 16; off > 0; off >>= 1)
        sse += __shfl_xor_sync(0xFFFFFFFFu, sse, off);
    if ((threadIdx.x & 31) == 0)
        atomicAdd(&g_sse, (double)sse);

    // ---- last block finalizes loss & perplexity ----------------------------
    __threadfence();
    __syncthreads();
    __shared__ unsigned int s_last;
    if (threadIdx.x == 0)
        s_last = (atomicAdd(&g_done, 1u) == gridDim.x - 1u) ? 1u : 0u;
    __syncthreads();
    if (s_last) {
        __threadfence();
        __shared__ float red[THREADS];
        float acc = 0.f;
        for (int b = threadIdx.x; b < KC; b += THREADS) {
            float pb = (float)g_hist[b] * (1.0f / (float)NROWS);
            acc += pb * logf(pb + 1e-10f);
        }
        red[threadIdx.x] = acc;
        __syncthreads();
        for (int off = THREADS / 2; off > 0; off >>= 1) {
            if (threadIdx.x < off) red[threadIdx.x] += red[threadIdx.x + off];
            __syncthreads();
        }
        if (threadIdx.x == 0) {
            out[0]      = (float)(1.25 * (g_sse * (1.0 / (double)NQ)));
            out[1 + NQ] = expf(-red[0]);
        }
    }
}

extern "C" void kernel_launch(void* const* d_in, const int* in_sizes, int n_in,
                              void* d_out, int out_size)
{
    const float* inp = (const float*)d_in[0];
    const float* emb = (const float*)d_in[1];
    if (n_in >= 2 && in_sizes[0] == KC * DIM) {
        const float* t = inp; inp = emb; emb = t;
    }
    float* out = (float*)d_out;

    const int smem_bytes = SMEM_FLOATS * sizeof(float);  // 141,312 B
    cudaFuncSetAttribute(vq_fused_kernel,
                         cudaFuncAttributeMaxDynamicSharedMemorySize,
                         smem_bytes);

    init_kernel<<<1, 512>>>();
    vq_fused_kernel<<<GRID, THREADS, smem_bytes>>>(inp, emb, out);
}